// round 13
// baseline (speedup 1.0000x reference)
#include <cuda_runtime.h>
#include <cuda_bf16.h>
#include <cstdint>

#define Bn   16
#define Rn   10
#define Nn   512
#define DE   256
#define DR   64
#define DOUT 256
#define INDIM 3200
#define RELS  320
#define GB   4              // batches per pipeline group
#define NG   (Bn / GB)      // 4 groups

// bf16 scratch
__device__ __align__(16) __nv_bfloat16 g_A [(size_t)Bn * Rn * Nn * Nn];
__device__ __align__(16) __nv_bfloat16 g_Zb[(size_t)Bn * Rn * DOUT * Nn];
__device__ __align__(16) __nv_bfloat16 g_N [(size_t)Bn * Nn * DE];
__device__ __align__(16) __nv_bfloat16 g_W [(size_t)DOUT * INDIM];
__device__ float g_V[Bn * Rn * DOUT];
__device__ float g_P[2 * (size_t)Bn * Nn * DOUT];

// ---- k_zc: k=32 stages, RS=40 halves ----
#define RSZ 40
#define TILE_Z  (128 * RSZ * 2)
#define STAGE_Z (2 * TILE_Z)
#define KZ_SMEM (3 * STAGE_Z + Rn * 128 * 4)
#define GEMMB 32            // per group: 8 tiles x GB batches
#define CONVB 96

// ---- k_main: CTA 128x128, 4 warps of 64x64, k=32 3-stage ----
#define RSM 40
#define TILE_MA (128 * RSM * 2)
#define STAGE_M (2 * TILE_MA)
#define KM_SMEM (3 * STAGE_M)

__device__ __forceinline__ uint32_t smem_u32(const void* p) {
    uint32_t a;
    asm("{ .reg .u64 t; cvta.to.shared.u64 t, %1; cvt.u32.u64 %0, t; }"
        : "=r"(a) : "l"(p));
    return a;
}

#define CP_ASYNC16(dst_u32, src) \
    asm volatile("cp.async.cg.shared.global [%0], [%1], 16;" \
                 :: "r"(dst_u32), "l"(src) : "memory")
#define CP_COMMIT() asm volatile("cp.async.commit_group;" ::: "memory")
#define CP_WAIT1()  asm volatile("cp.async.wait_group 1;" ::: "memory")

#define LDMX4(r0, r1, r2, r3, addr) \
    asm volatile("ldmatrix.sync.aligned.m8n8.x4.shared.b16 {%0,%1,%2,%3}, [%4];" \
                 : "=r"(r0), "=r"(r1), "=r"(r2), "=r"(r3) : "r"(addr))

__device__ __forceinline__ void mma16(float* c, const uint32_t* a,
                                      uint32_t b0, uint32_t b1) {
    asm volatile(
        "mma.sync.aligned.m16n8k16.row.col.f32.bf16.bf16.f32 "
        "{%0,%1,%2,%3}, {%4,%5,%6,%7}, {%8,%9}, {%0,%1,%2,%3};"
        : "+f"(c[0]), "+f"(c[1]), "+f"(c[2]), "+f"(c[3])
        : "r"(a[0]), "r"(a[1]), "r"(a[2]), "r"(a[3]), "r"(b0), "r"(b1));
}

__device__ __forceinline__ void compute32(uint32_t st,
                                          const uint32_t (&aoff)[2][2],
                                          const uint32_t (&boff)[4][2],
                                          float (&acc)[2][8][4]) {
    uint32_t a[2][2][4], bq[4][2][4];
#pragma unroll
    for (int mi = 0; mi < 2; mi++)
#pragma unroll
        for (int kk = 0; kk < 2; kk++)
            LDMX4(a[mi][kk][0], a[mi][kk][1], a[mi][kk][2], a[mi][kk][3],
                  st + aoff[mi][kk]);
#pragma unroll
    for (int nb = 0; nb < 4; nb++)
#pragma unroll
        for (int kk = 0; kk < 2; kk++)
            LDMX4(bq[nb][kk][0], bq[nb][kk][1], bq[nb][kk][2], bq[nb][kk][3],
                  st + boff[nb][kk]);
#pragma unroll
    for (int kk = 0; kk < 2; kk++)
#pragma unroll
        for (int mi = 0; mi < 2; mi++)
#pragma unroll
            for (int ni = 0; ni < 8; ni++) {
                const int nb = ni >> 1, odd = ni & 1;
                mma16(acc[mi][ni], a[mi][kk], bq[nb][kk][odd], bq[nb][kk][2 + odd]);
            }
}

// ---------------------------------------------------------------------------
// k_pre: node/W -> bf16, v[b][r][o] (fp32).  grid 1280 x 256.
// ---------------------------------------------------------------------------
__global__ void k_pre(const float* __restrict__ node, const float* __restrict__ W,
                      const float* __restrict__ rel) {
    const size_t stride = (size_t)gridDim.x * blockDim.x;
    const size_t t0 = (size_t)blockIdx.x * blockDim.x + threadIdx.x;

    const size_t nnode = (size_t)Bn * Nn * DE / 4;
    for (size_t i = t0; i < nnode; i += stride) {
        float4 v = reinterpret_cast<const float4*>(node)[i];
        __nv_bfloat162 p0 = __floats2bfloat162_rn(v.x, v.y);
        __nv_bfloat162 p1 = __floats2bfloat162_rn(v.z, v.w);
        uint2 u = { *reinterpret_cast<unsigned*>(&p0), *reinterpret_cast<unsigned*>(&p1) };
        reinterpret_cast<uint2*>(g_N)[i] = u;
    }
    const size_t nw = (size_t)DOUT * INDIM / 4;
    for (size_t i = t0; i < nw; i += stride) {
        float4 v = reinterpret_cast<const float4*>(W)[i];
        __nv_bfloat162 p0 = __floats2bfloat162_rn(v.x, v.y);
        __nv_bfloat162 p1 = __floats2bfloat162_rn(v.z, v.w);
        uint2 u = { *reinterpret_cast<unsigned*>(&p0), *reinterpret_cast<unsigned*>(&p1) };
        reinterpret_cast<uint2*>(g_W)[i] = u;
    }
    if (blockIdx.x < Bn * Rn) {
        const int br = blockIdx.x, r = br % Rn;
        const int o = threadIdx.x;
        const float* wr = W + (size_t)o * INDIM + r * RELS + DE;
        const float* rp = rel + (size_t)br * DR;
        float s = 0.f;
#pragma unroll
        for (int d = 0; d < DR; d++) s += rp[d] * wr[d];
        g_V[br * DOUT + o] = s;
    }
}

// ---------------------------------------------------------------------------
// k_zc(base_b): blocks [0,32): Z GEMM for batches [base_b, base_b+GB);
//               blocks [32,128): adj fp32 -> bf16 for same batches.
// ---------------------------------------------------------------------------
__global__ __launch_bounds__(256, 2) void k_zc(const float* __restrict__ adj,
                                               int base_b) {
    const int tid = threadIdx.x;

    if (blockIdx.x >= GEMMB) {
        const size_t grp  = (size_t)GB * Rn * Nn * Nn / 4;   // float4 per group
        const size_t base = (size_t)base_b * Rn * Nn * Nn / 4;
        const size_t stride = (size_t)CONVB * 256;
        for (size_t i = (size_t)(blockIdx.x - GEMMB) * 256 + tid; i < grp; i += stride) {
            float4 v = reinterpret_cast<const float4*>(adj)[base + i];
            __nv_bfloat162 p0 = __floats2bfloat162_rn(v.x, v.y);
            __nv_bfloat162 p1 = __floats2bfloat162_rn(v.z, v.w);
            uint2 u = { *reinterpret_cast<unsigned*>(&p0), *reinterpret_cast<unsigned*>(&p1) };
            reinterpret_cast<uint2*>(g_A)[base + i] = u;
        }
        return;
    }

    extern __shared__ __align__(16) char smc[];
    const uint32_t sb = smem_u32(smc);
    float* vs = reinterpret_cast<float*>(smc + 3 * STAGE_Z);

    const int lane = tid & 31, warp = tid >> 5;
    const int wm = warp & 3, wn = warp >> 2;
    const int bid = blockIdx.x;
    const int b = base_b + (bid >> 3), tt = bid & 7;
    const int mm0 = (tt & 3) * 128;
    const int o0  = (tt >> 2) * 128;

#pragma unroll
    for (int i = 0; i < 5; i++) {
        const int idx = i * 256 + tid;
        vs[idx] = g_V[(b * Rn + (idx >> 7)) * DOUT + o0 + (idx & 127)];
    }

    const int t8 = lane >> 3;
    const int rIn = (t8 & 1) * 8 + (lane & 7), kIn = (t8 >> 1) * 8;
    uint32_t aoff[2][2], boff[4][2];
#pragma unroll
    for (int mi = 0; mi < 2; mi++)
#pragma unroll
        for (int kk = 0; kk < 2; kk++)
            aoff[mi][kk] = ((wm * 32 + mi * 16 + rIn) * RSZ + kk * 16 + kIn) * 2;
#pragma unroll
    for (int nb = 0; nb < 4; nb++)
#pragma unroll
        for (int kk = 0; kk < 2; kk++)
            boff[nb][kk] = TILE_Z + ((wn * 64 + nb * 16 + rIn) * RSZ + kk * 16 + kIn) * 2;

    float acc[2][8][4];
#pragma unroll
    for (int mi = 0; mi < 2; mi++)
#pragma unroll
        for (int ni = 0; ni < 8; ni++)
#pragma unroll
            for (int q = 0; q < 4; q++) acc[mi][ni][q] = 0.f;

    auto cpchunk = [&](int j) {
        const int rj = j >> 3, kk = j & 7;
        const __nv_bfloat16* Ag = g_W + (size_t)o0 * INDIM + rj * RELS + kk * 32;
        const __nv_bfloat16* Bg = g_N + (size_t)(b * Nn + mm0) * DE + kk * 32;
        const uint32_t st = sb + (j % 3) * STAGE_Z;
#pragma unroll
        for (int q = 0; q < 2; q++) {
            const int idx = q * 256 + tid, r = idx >> 2, s = idx & 3;
            CP_ASYNC16(st + (r * RSZ + s * 8) * 2, Ag + (size_t)r * INDIM + s * 8);
            CP_ASYNC16(st + TILE_Z + (r * RSZ + s * 8) * 2, Bg + (size_t)r * DE + s * 8);
        }
    };

    cpchunk(0); CP_COMMIT();
    cpchunk(1); CP_COMMIT();

    const int J = Rn * 8;
    const int r4 = lane >> 2, c2 = 2 * (lane & 3);
    for (int j = 0; j < J; j++) {
        CP_WAIT1();
        __syncthreads();
        if (j + 2 < J) cpchunk(j + 2);
        CP_COMMIT();
        compute32(sb + (j % 3) * STAGE_Z, aoff, boff, acc);
        if ((j & 7) == 7) {
            const int r = j >> 3;
            __nv_bfloat16* zr = g_Zb + (size_t)(b * Rn + r) * (DOUT * Nn);
#pragma unroll
            for (int mi = 0; mi < 2; mi++) {
#pragma unroll
                for (int ni = 0; ni < 8; ni++) {
                    const int orow = wm * 32 + mi * 16 + r4;
                    const int mcol = wn * 64 + ni * 8 + c2;
                    __nv_bfloat16* zp = zr + (size_t)(o0 + orow) * Nn + mm0 + mcol;
                    const float v0 = vs[r * 128 + orow];
                    __nv_bfloat162 lo = __floats2bfloat162_rn(acc[mi][ni][0] + v0,
                                                              acc[mi][ni][1] + v0);
                    *reinterpret_cast<__nv_bfloat162*>(zp) = lo;
                    const float v1 = vs[r * 128 + orow + 8];
                    __nv_bfloat162 hi = __floats2bfloat162_rn(acc[mi][ni][2] + v1,
                                                              acc[mi][ni][3] + v1);
                    *reinterpret_cast<__nv_bfloat162*>(zp + (size_t)8 * Nn) = hi;
#pragma unroll
                    for (int q = 0; q < 4; q++) acc[mi][ni][q] = 0.f;
                }
            }
        }
    }
}

// ---------------------------------------------------------------------------
// k_main(base_b): split-K2, CTA 128x128, 4 warps of 64x64.
// grid (4 n, 2 o, GB * 2 ks), 128 threads, 2 CTAs/SM.
// ---------------------------------------------------------------------------
__global__ __launch_bounds__(128, 2) void k_main(int base_b) {
    extern __shared__ __align__(16) char smc[];
    const uint32_t sb = smem_u32(smc);

    const int tid = threadIdx.x, lane = tid & 31, warp = tid >> 5;
    const int wm = warp & 1, wn = warp >> 1;
    const int zz = blockIdx.z;
    const int b = base_b + (zz & (GB - 1)), ks = zz / GB;
    const int n0 = blockIdx.x * 128, o0 = blockIdx.y * 128;
    const int rbase = ks * 5;

    const int t8 = lane >> 3;
    const int rIn = (t8 & 1) * 8 + (lane & 7), kIn = (t8 >> 1) * 8;
    uint32_t aoff[4][2], boff[4][2];
#pragma unroll
    for (int mi = 0; mi < 4; mi++)
#pragma unroll
        for (int kk = 0; kk < 2; kk++)
            aoff[mi][kk] = ((wm * 64 + mi * 16 + rIn) * RSM + kk * 16 + kIn) * 2;
#pragma unroll
    for (int nb = 0; nb < 4; nb++)
#pragma unroll
        for (int kk = 0; kk < 2; kk++)
            boff[nb][kk] = TILE_MA + ((wn * 64 + nb * 16 + rIn) * RSM + kk * 16 + kIn) * 2;

    float acc[4][8][4];
#pragma unroll
    for (int mi = 0; mi < 4; mi++)
#pragma unroll
        for (int ni = 0; ni < 8; ni++)
#pragma unroll
            for (int q = 0; q < 4; q++) acc[mi][ni][q] = 0.f;

    auto cpchunk = [&](int j) {
        const int rj = rbase + (j >> 4), kk = j & 15;
        const __nv_bfloat16* Ag = g_A + ((size_t)(b * Rn + rj) * Nn + n0) * Nn + kk * 32;
        const __nv_bfloat16* Bg = g_Zb + ((size_t)(b * Rn + rj) * DOUT + o0) * Nn + kk * 32;
        const uint32_t st = sb + (j % 3) * STAGE_M;
#pragma unroll
        for (int q = 0; q < 4; q++) {
            const int idx = q * 128 + tid, r = idx >> 2, s = idx & 3;
            CP_ASYNC16(st + (r * RSM + s * 8) * 2, Ag + (size_t)r * Nn + s * 8);
            CP_ASYNC16(st + TILE_MA + (r * RSM + s * 8) * 2, Bg + (size_t)r * Nn + s * 8);
        }
    };

    cpchunk(0); CP_COMMIT();
    cpchunk(1); CP_COMMIT();

    const int J = 80;
    for (int j = 0; j < J; j++) {
        CP_WAIT1();
        __syncthreads();
        if (j + 2 < J) cpchunk(j + 2);
        CP_COMMIT();
        const uint32_t st = sb + (j % 3) * STAGE_M;
        uint32_t a[4][2][4], bq[4][2][4];
#pragma unroll
        for (int mi = 0; mi < 4; mi++)
#pragma unroll
            for (int kk = 0; kk < 2; kk++)
                LDMX4(a[mi][kk][0], a[mi][kk][1], a[mi][kk][2], a[mi][kk][3],
                      st + aoff[mi][kk]);
#pragma unroll
        for (int nb = 0; nb < 4; nb++)
#pragma unroll
            for (int kk = 0; kk < 2; kk++)
                LDMX4(bq[nb][kk][0], bq[nb][kk][1], bq[nb][kk][2], bq[nb][kk][3],
                      st + boff[nb][kk]);
#pragma unroll
        for (int kk = 0; kk < 2; kk++)
#pragma unroll
            for (int mi = 0; mi < 4; mi++)
#pragma unroll
                for (int ni = 0; ni < 8; ni++) {
                    const int nb = ni >> 1, odd = ni & 1;
                    mma16(acc[mi][ni], a[mi][kk], bq[nb][kk][odd], bq[nb][kk][2 + odd]);
                }
    }

    float* P = g_P + (size_t)ks * Bn * Nn * DOUT;
    const int r4 = lane >> 2, c2 = 2 * (lane & 3);
#pragma unroll
    for (int mi = 0; mi < 4; mi++) {
#pragma unroll
        for (int ni = 0; ni < 8; ni++) {
            const int nrow = wm * 64 + mi * 16 + r4;
            const int ocol = wn * 64 + ni * 8 + c2;
            float* op = P + ((size_t)(b * Nn + n0 + nrow)) * DOUT + o0 + ocol;
            float2 lo = { acc[mi][ni][0], acc[mi][ni][1] };
            *reinterpret_cast<float2*>(op) = lo;
            float2 hi = { acc[mi][ni][2], acc[mi][ni][3] };
            *reinterpret_cast<float2*>(op + (size_t)8 * DOUT) = hi;
        }
    }
}

// ---------------------------------------------------------------------------
__global__ void k_red(const float* __restrict__ bias, float* __restrict__ out) {
    const size_t i = (size_t)blockIdx.x * blockDim.x + threadIdx.x;
    const size_t half = (size_t)Bn * Nn * DOUT / 4;
    float4 p0 = reinterpret_cast<const float4*>(g_P)[i];
    float4 p1 = reinterpret_cast<const float4*>(g_P)[i + half];
    float4 bb = reinterpret_cast<const float4*>(bias)[i & (DOUT / 4 - 1)];
    float4 v = { p0.x + p1.x + bb.x, p0.y + p1.y + bb.y,
                 p0.z + p1.z + bb.z, p0.w + p1.w + bb.w };
    reinterpret_cast<float4*>(out)[i] = v;
}

// ---------------------------------------------------------------------------
extern "C" void kernel_launch(void* const* d_in, const int* in_sizes, int n_in,
                              void* d_out, int out_size) {
    const float *node = nullptr, *rel = nullptr, *adj = nullptr,
                *W = nullptr, *bias = nullptr;
    for (int i = 0; i < n_in; i++) {
        const int s = in_sizes[i];
        if      (s == Bn * Nn * DE)      node = (const float*)d_in[i];
        else if (s == Bn * Rn * DR)      rel  = (const float*)d_in[i];
        else if (s == Bn * Rn * Nn * Nn) adj  = (const float*)d_in[i];
        else if (s == DOUT * INDIM)      W    = (const float*)d_in[i];
        else if (s == DOUT)              bias = (const float*)d_in[i];
    }

    // One-time infra init (same graph captured every call — deterministic).
    static bool init = false;
    static cudaStream_t s1, s2;
    static cudaEvent_t evRoot, evZ[NG], evM;
    if (!init) {
        cudaStreamCreateWithFlags(&s1, cudaStreamNonBlocking);
        cudaStreamCreateWithFlags(&s2, cudaStreamNonBlocking);
        cudaEventCreateWithFlags(&evRoot, cudaEventDisableTiming);
        for (int g = 0; g < NG; g++)
            cudaEventCreateWithFlags(&evZ[g], cudaEventDisableTiming);
        cudaEventCreateWithFlags(&evM, cudaEventDisableTiming);
        cudaFuncSetAttribute(k_zc,   cudaFuncAttributeMaxDynamicSharedMemorySize, KZ_SMEM);
        cudaFuncSetAttribute(k_main, cudaFuncAttributeMaxDynamicSharedMemorySize, KM_SMEM);
        init = true;
    }

    // Root work on the (captured) default stream.
    k_pre<<<1280, 256>>>(node, W, rel);
    cudaEventRecord(evRoot, 0);

    // s1: conversion + Z GEMM per group, sequential.
    cudaStreamWaitEvent(s1, evRoot, 0);
    for (int g = 0; g < NG; g++) {
        k_zc<<<GEMMB + CONVB, 256, KZ_SMEM, s1>>>(adj, g * GB);
        cudaEventRecord(evZ[g], s1);
    }

    // s2: main GEMM per group, each gated on its group's Z.
    for (int g = 0; g < NG; g++) {
        cudaStreamWaitEvent(s2, evZ[g], 0);
        k_main<<<dim3(4, 2, GB * 2), 128, KM_SMEM, s2>>>(g * GB);
    }
    cudaEventRecord(evM, s2);

    // Join back to default stream; final reduction.
    cudaStreamWaitEvent(0, evM, 0);
    k_red<<<(Bn * Nn * DOUT / 4) / 256, 256>>>(bias, (float*)d_out);
}

// round 14
// speedup vs baseline: 1.9104x; 1.9104x over previous
#include <cuda_runtime.h>
#include <cuda_bf16.h>
#include <cstdint>

#define Bn   16
#define Rn   10
#define Nn   512
#define DE   256
#define DR   64
#define DOUT 256
#define INDIM 3200
#define RELS  320

// bf16 scratch
__device__ __align__(16) __nv_bfloat16 g_A [(size_t)Bn * Rn * Nn * Nn];
__device__ __align__(16) __nv_bfloat16 g_Zb[(size_t)Bn * Rn * DOUT * Nn];
__device__ __align__(16) __nv_bfloat16 g_N [(size_t)Bn * Nn * DE];
__device__ __align__(16) __nv_bfloat16 g_W [(size_t)DOUT * INDIM];
__device__ float g_V[Bn * Rn * DOUT];
__device__ float g_P[2 * (size_t)Bn * Nn * DOUT];

// ---- k_zc: k=32 stages, RS=40 halves, 4-stage ring ----
#define RSZ 40
#define TILE_Z  (128 * RSZ * 2)
#define STAGE_Z (2 * TILE_Z)
#define KZ_SMEM (4 * STAGE_Z + 5 * 128 * 4)   // 84480 B
#define GEMMB 256                              // 16 b x 8 tiles x 2 r-halves
#define CONVB 320

// ---- k_main: CTA 128x128, 4 warps of 64x64, k=32 4-stage ring ----
#define RSM 40
#define TILE_MA (128 * RSM * 2)
#define STAGE_M (2 * TILE_MA)
#define KM_SMEM (4 * STAGE_M)                  // 81920 B

__device__ __forceinline__ uint32_t smem_u32(const void* p) {
    uint32_t a;
    asm("{ .reg .u64 t; cvta.to.shared.u64 t, %1; cvt.u32.u64 %0, t; }"
        : "=r"(a) : "l"(p));
    return a;
}

#define CP_ASYNC16(dst_u32, src) \
    asm volatile("cp.async.cg.shared.global [%0], [%1], 16;" \
                 :: "r"(dst_u32), "l"(src) : "memory")
#define CP_COMMIT() asm volatile("cp.async.commit_group;" ::: "memory")
#define CP_WAIT2()  asm volatile("cp.async.wait_group 2;" ::: "memory")

#define LDMX4(r0, r1, r2, r3, addr) \
    asm volatile("ldmatrix.sync.aligned.m8n8.x4.shared.b16 {%0,%1,%2,%3}, [%4];" \
                 : "=r"(r0), "=r"(r1), "=r"(r2), "=r"(r3) : "r"(addr))

__device__ __forceinline__ void mma16(float* c, const uint32_t* a,
                                      uint32_t b0, uint32_t b1) {
    asm volatile(
        "mma.sync.aligned.m16n8k16.row.col.f32.bf16.bf16.f32 "
        "{%0,%1,%2,%3}, {%4,%5,%6,%7}, {%8,%9}, {%0,%1,%2,%3};"
        : "+f"(c[0]), "+f"(c[1]), "+f"(c[2]), "+f"(c[3])
        : "r"(a[0]), "r"(a[1]), "r"(a[2]), "r"(a[3]), "r"(b0), "r"(b1));
}

__device__ __forceinline__ void compute32(uint32_t st,
                                          const uint32_t (&aoff)[2][2],
                                          const uint32_t (&boff)[4][2],
                                          float (&acc)[2][8][4]) {
    uint32_t a[2][2][4], bq[4][2][4];
#pragma unroll
    for (int mi = 0; mi < 2; mi++)
#pragma unroll
        for (int kk = 0; kk < 2; kk++)
            LDMX4(a[mi][kk][0], a[mi][kk][1], a[mi][kk][2], a[mi][kk][3],
                  st + aoff[mi][kk]);
#pragma unroll
    for (int nb = 0; nb < 4; nb++)
#pragma unroll
        for (int kk = 0; kk < 2; kk++)
            LDMX4(bq[nb][kk][0], bq[nb][kk][1], bq[nb][kk][2], bq[nb][kk][3],
                  st + boff[nb][kk]);
#pragma unroll
    for (int kk = 0; kk < 2; kk++)
#pragma unroll
        for (int mi = 0; mi < 2; mi++)
#pragma unroll
            for (int ni = 0; ni < 8; ni++) {
                const int nb = ni >> 1, odd = ni & 1;
                mma16(acc[mi][ni], a[mi][kk], bq[nb][kk][odd], bq[nb][kk][2 + odd]);
            }
}

// ---------------------------------------------------------------------------
// k_pre: node/W -> bf16, v[b][r][o] (fp32).  grid 1280 x 256.
// ---------------------------------------------------------------------------
__global__ void k_pre(const float* __restrict__ node, const float* __restrict__ W,
                      const float* __restrict__ rel) {
    const size_t stride = (size_t)gridDim.x * blockDim.x;
    const size_t t0 = (size_t)blockIdx.x * blockDim.x + threadIdx.x;

    const size_t nnode = (size_t)Bn * Nn * DE / 4;
    for (size_t i = t0; i < nnode; i += stride) {
        float4 v = reinterpret_cast<const float4*>(node)[i];
        __nv_bfloat162 p0 = __floats2bfloat162_rn(v.x, v.y);
        __nv_bfloat162 p1 = __floats2bfloat162_rn(v.z, v.w);
        uint2 u = { *reinterpret_cast<unsigned*>(&p0), *reinterpret_cast<unsigned*>(&p1) };
        reinterpret_cast<uint2*>(g_N)[i] = u;
    }
    const size_t nw = (size_t)DOUT * INDIM / 4;
    for (size_t i = t0; i < nw; i += stride) {
        float4 v = reinterpret_cast<const float4*>(W)[i];
        __nv_bfloat162 p0 = __floats2bfloat162_rn(v.x, v.y);
        __nv_bfloat162 p1 = __floats2bfloat162_rn(v.z, v.w);
        uint2 u = { *reinterpret_cast<unsigned*>(&p0), *reinterpret_cast<unsigned*>(&p1) };
        reinterpret_cast<uint2*>(g_W)[i] = u;
    }
    if (blockIdx.x < Bn * Rn) {
        const int br = blockIdx.x, r = br % Rn;
        const int o = threadIdx.x;
        const float* wr = W + (size_t)o * INDIM + r * RELS + DE;
        const float* rp = rel + (size_t)br * DR;
        float s = 0.f;
#pragma unroll
        for (int d = 0; d < DR; d++) s += rp[d] * wr[d];
        g_V[br * DOUT + o] = s;
    }
}

// ---------------------------------------------------------------------------
// k_zc: blocks [0,256): Z GEMM (one r-half each); blocks [256,576): adj->bf16.
// GEMM block: CTA tile o 128 x m 128, 5 relations (rbase..rbase+4), 40 chunks.
// ---------------------------------------------------------------------------
__global__ __launch_bounds__(256, 2) void k_zc(const float* __restrict__ adj) {
    const int tid = threadIdx.x;

    if (blockIdx.x >= GEMMB) {
        const size_t stride = (size_t)CONVB * 256;
        const size_t nq = (size_t)Bn * Rn * Nn * Nn / 4;
        for (size_t i = (size_t)(blockIdx.x - GEMMB) * 256 + tid; i < nq; i += stride) {
            float4 v = reinterpret_cast<const float4*>(adj)[i];
            __nv_bfloat162 p0 = __floats2bfloat162_rn(v.x, v.y);
            __nv_bfloat162 p1 = __floats2bfloat162_rn(v.z, v.w);
            uint2 u = { *reinterpret_cast<unsigned*>(&p0), *reinterpret_cast<unsigned*>(&p1) };
            reinterpret_cast<uint2*>(g_A)[i] = u;
        }
        return;
    }

    extern __shared__ __align__(16) char smc[];
    const uint32_t sb = smem_u32(smc);
    float* vs = reinterpret_cast<float*>(smc + 4 * STAGE_Z);   // [5][128]

    const int lane = tid & 31, warp = tid >> 5;
    const int wm = warp & 3, wn = warp >> 2;
    const int bid = blockIdx.x;
    const int b = bid >> 4, tt = bid & 15;
    const int rbase = (tt >> 3) * 5;
    const int mm0 = (tt & 3) * 128;
    const int o0  = ((tt >> 2) & 1) * 128;

    // stage v[rbase..rbase+4][o-tile]
    if (tid < 128) {
#pragma unroll
        for (int rr = 0; rr < 5; rr++)
            vs[rr * 128 + tid] = g_V[(b * Rn + rbase + rr) * DOUT + o0 + tid];
    }

    const int t8 = lane >> 3;
    const int rIn = (t8 & 1) * 8 + (lane & 7), kIn = (t8 >> 1) * 8;
    uint32_t aoff[2][2], boff[4][2];
#pragma unroll
    for (int mi = 0; mi < 2; mi++)
#pragma unroll
        for (int kk = 0; kk < 2; kk++)
            aoff[mi][kk] = ((wm * 32 + mi * 16 + rIn) * RSZ + kk * 16 + kIn) * 2;
#pragma unroll
    for (int nb = 0; nb < 4; nb++)
#pragma unroll
        for (int kk = 0; kk < 2; kk++)
            boff[nb][kk] = TILE_Z + ((wn * 64 + nb * 16 + rIn) * RSZ + kk * 16 + kIn) * 2;

    float acc[2][8][4];
#pragma unroll
    for (int mi = 0; mi < 2; mi++)
#pragma unroll
        for (int ni = 0; ni < 8; ni++)
#pragma unroll
            for (int q = 0; q < 4; q++) acc[mi][ni][q] = 0.f;

    auto cpchunk = [&](int j) {
        const int rj = rbase + (j >> 3), kk = j & 7;
        const __nv_bfloat16* Ag = g_W + (size_t)o0 * INDIM + rj * RELS + kk * 32;
        const __nv_bfloat16* Bg = g_N + (size_t)(b * Nn + mm0) * DE + kk * 32;
        const uint32_t st = sb + (j & 3) * STAGE_Z;
#pragma unroll
        for (int q = 0; q < 2; q++) {
            const int idx = q * 256 + tid, r = idx >> 2, s = idx & 3;
            CP_ASYNC16(st + (r * RSZ + s * 8) * 2, Ag + (size_t)r * INDIM + s * 8);
            CP_ASYNC16(st + TILE_Z + (r * RSZ + s * 8) * 2, Bg + (size_t)r * DE + s * 8);
        }
    };

    cpchunk(0); CP_COMMIT();
    cpchunk(1); CP_COMMIT();
    cpchunk(2); CP_COMMIT();

    const int J = 40;
    const int r4 = lane >> 2, c2 = 2 * (lane & 3);
    for (int j = 0; j < J; j++) {
        CP_WAIT2();                       // group j complete (j+1, j+2 pending)
        __syncthreads();                  // all past compute(j-1): stage (j+3)&3 free
        if (j + 3 < J) cpchunk(j + 3);
        CP_COMMIT();
        compute32(sb + (j & 3) * STAGE_Z, aoff, boff, acc);
        if ((j & 7) == 7) {
            const int rr = j >> 3;
            __nv_bfloat16* zr = g_Zb + (size_t)(b * Rn + rbase + rr) * (DOUT * Nn);
#pragma unroll
            for (int mi = 0; mi < 2; mi++) {
#pragma unroll
                for (int ni = 0; ni < 8; ni++) {
                    const int orow = wm * 32 + mi * 16 + r4;
                    const int mcol = wn * 64 + ni * 8 + c2;
                    __nv_bfloat16* zp = zr + (size_t)(o0 + orow) * Nn + mm0 + mcol;
                    const float v0 = vs[rr * 128 + orow];
                    __nv_bfloat162 lo = __floats2bfloat162_rn(acc[mi][ni][0] + v0,
                                                              acc[mi][ni][1] + v0);
                    *reinterpret_cast<__nv_bfloat162*>(zp) = lo;
                    const float v1 = vs[rr * 128 + orow + 8];
                    __nv_bfloat162 hi = __floats2bfloat162_rn(acc[mi][ni][2] + v1,
                                                              acc[mi][ni][3] + v1);
                    *reinterpret_cast<__nv_bfloat162*>(zp + (size_t)8 * Nn) = hi;
#pragma unroll
                    for (int q = 0; q < 4; q++) acc[mi][ni][q] = 0.f;
                }
            }
        }
    }
}

// ---------------------------------------------------------------------------
// k_main: split-K2, CTA 128x128, 4 warps of 64x64, 4-stage ring.
// grid (4 n, 2 o, 16 b * 2 ks), 128 threads, 2 CTAs/SM.
// ---------------------------------------------------------------------------
__global__ __launch_bounds__(128, 2) void k_main() {
    extern __shared__ __align__(16) char smc[];
    const uint32_t sb = smem_u32(smc);

    const int tid = threadIdx.x, lane = tid & 31, warp = tid >> 5;
    const int wm = warp & 1, wn = warp >> 1;
    const int zz = blockIdx.z;
    const int b = zz & 15, ks = zz >> 4;
    const int n0 = blockIdx.x * 128, o0 = blockIdx.y * 128;
    const int rbase = ks * 5;

    const int t8 = lane >> 3;
    const int rIn = (t8 & 1) * 8 + (lane & 7), kIn = (t8 >> 1) * 8;
    uint32_t aoff[4][2], boff[4][2];
#pragma unroll
    for (int mi = 0; mi < 4; mi++)
#pragma unroll
        for (int kk = 0; kk < 2; kk++)
            aoff[mi][kk] = ((wm * 64 + mi * 16 + rIn) * RSM + kk * 16 + kIn) * 2;
#pragma unroll
    for (int nb = 0; nb < 4; nb++)
#pragma unroll
        for (int kk = 0; kk < 2; kk++)
            boff[nb][kk] = TILE_MA + ((wn * 64 + nb * 16 + rIn) * RSM + kk * 16 + kIn) * 2;

    float acc[4][8][4];
#pragma unroll
    for (int mi = 0; mi < 4; mi++)
#pragma unroll
        for (int ni = 0; ni < 8; ni++)
#pragma unroll
            for (int q = 0; q < 4; q++) acc[mi][ni][q] = 0.f;

    auto cpchunk = [&](int j) {
        const int rj = rbase + (j >> 4), kk = j & 15;
        const __nv_bfloat16* Ag = g_A + ((size_t)(b * Rn + rj) * Nn + n0) * Nn + kk * 32;
        const __nv_bfloat16* Bg = g_Zb + ((size_t)(b * Rn + rj) * DOUT + o0) * Nn + kk * 32;
        const uint32_t st = sb + (j & 3) * STAGE_M;
#pragma unroll
        for (int q = 0; q < 4; q++) {
            const int idx = q * 128 + tid, r = idx >> 2, s = idx & 3;
            CP_ASYNC16(st + (r * RSM + s * 8) * 2, Ag + (size_t)r * Nn + s * 8);
            CP_ASYNC16(st + TILE_MA + (r * RSM + s * 8) * 2, Bg + (size_t)r * Nn + s * 8);
        }
    };

    cpchunk(0); CP_COMMIT();
    cpchunk(1); CP_COMMIT();
    cpchunk(2); CP_COMMIT();

    const int J = 80;
    for (int j = 0; j < J; j++) {
        CP_WAIT2();
        __syncthreads();
        if (j + 3 < J) cpchunk(j + 3);
        CP_COMMIT();
        const uint32_t st = sb + (j & 3) * STAGE_M;
        uint32_t a[4][2][4], bq[4][2][4];
#pragma unroll
        for (int mi = 0; mi < 4; mi++)
#pragma unroll
            for (int kk = 0; kk < 2; kk++)
                LDMX4(a[mi][kk][0], a[mi][kk][1], a[mi][kk][2], a[mi][kk][3],
                      st + aoff[mi][kk]);
#pragma unroll
        for (int nb = 0; nb < 4; nb++)
#pragma unroll
            for (int kk = 0; kk < 2; kk++)
                LDMX4(bq[nb][kk][0], bq[nb][kk][1], bq[nb][kk][2], bq[nb][kk][3],
                      st + boff[nb][kk]);
#pragma unroll
        for (int kk = 0; kk < 2; kk++)
#pragma unroll
            for (int mi = 0; mi < 4; mi++)
#pragma unroll
                for (int ni = 0; ni < 8; ni++) {
                    const int nb = ni >> 1, odd = ni & 1;
                    mma16(acc[mi][ni], a[mi][kk], bq[nb][kk][odd], bq[nb][kk][2 + odd]);
                }
    }

    float* P = g_P + (size_t)ks * Bn * Nn * DOUT;
    const int r4 = lane >> 2, c2 = 2 * (lane & 3);
#pragma unroll
    for (int mi = 0; mi < 4; mi++) {
#pragma unroll
        for (int ni = 0; ni < 8; ni++) {
            const int nrow = wm * 64 + mi * 16 + r4;
            const int ocol = wn * 64 + ni * 8 + c2;
            float* op = P + ((size_t)(b * Nn + n0 + nrow)) * DOUT + o0 + ocol;
            float2 lo = { acc[mi][ni][0], acc[mi][ni][1] };
            *reinterpret_cast<float2*>(op) = lo;
            float2 hi = { acc[mi][ni][2], acc[mi][ni][3] };
            *reinterpret_cast<float2*>(op + (size_t)8 * DOUT) = hi;
        }
    }
}

// ---------------------------------------------------------------------------
__global__ void k_red(const float* __restrict__ bias, float* __restrict__ out) {
    const size_t i = (size_t)blockIdx.x * blockDim.x + threadIdx.x;
    const size_t half = (size_t)Bn * Nn * DOUT / 4;
    float4 p0 = reinterpret_cast<const float4*>(g_P)[i];
    float4 p1 = reinterpret_cast<const float4*>(g_P)[i + half];
    float4 bb = reinterpret_cast<const float4*>(bias)[i & (DOUT / 4 - 1)];
    float4 v = { p0.x + p1.x + bb.x, p0.y + p1.y + bb.y,
                 p0.z + p1.z + bb.z, p0.w + p1.w + bb.w };
    reinterpret_cast<float4*>(out)[i] = v;
}

// ---------------------------------------------------------------------------
extern "C" void kernel_launch(void* const* d_in, const int* in_sizes, int n_in,
                              void* d_out, int out_size) {
    const float *node = nullptr, *rel = nullptr, *adj = nullptr,
                *W = nullptr, *bias = nullptr;
    for (int i = 0; i < n_in; i++) {
        const int s = in_sizes[i];
        if      (s == Bn * Nn * DE)      node = (const float*)d_in[i];
        else if (s == Bn * Rn * DR)      rel  = (const float*)d_in[i];
        else if (s == Bn * Rn * Nn * Nn) adj  = (const float*)d_in[i];
        else if (s == DOUT * INDIM)      W    = (const float*)d_in[i];
        else if (s == DOUT)              bias = (const float*)d_in[i];
    }
    cudaFuncSetAttribute(k_zc,   cudaFuncAttributeMaxDynamicSharedMemorySize, KZ_SMEM);
    cudaFuncSetAttribute(k_main, cudaFuncAttributeMaxDynamicSharedMemorySize, KM_SMEM);

    k_pre <<<1280, 256>>>(node, W, rel);
    k_zc  <<<GEMMB + CONVB, 256, KZ_SMEM>>>(adj);
    k_main<<<dim3(4, 2, Bn * 2), 128, KM_SMEM>>>();
    k_red <<<(Bn * Nn * DOUT / 4) / 256, 256>>>(bias, (float*)d_out);
}